// round 14
// baseline (speedup 1.0000x reference)
#include <cuda_runtime.h>
#include <cuda_bf16.h>
#include <math.h>
#include <cstdint>

#define B_SZ 512
#define K_SZ 32
#define D_SZ 768
#define N_SENSES 200000
#define NEG_INF -1e30f

#define WARPS_PER_CTA 8
#define CTA_THREADS (WARPS_PER_CTA * 32)       // 256
#define ITEMS_PER_WARP (K_SZ / WARPS_PER_CTA)  // 4 candidates per warp
#define GRID_CTAS B_SZ                         // 1 sample per CTA -> 512 CTAs

// Global scratch. Counters use atomicInc wrap -> self-reset each full launch,
// deterministic under graph replay.
__device__ float    g_logits[B_SZ * K_SZ];
__device__ float    g_nll[B_SZ];
__device__ unsigned g_cnt[B_SZ];     // wraps at WARPS_PER_CTA-1 (8 warp arrivals)
__device__ unsigned g_done = 0;      // wraps at B_SZ-1

__global__ __launch_bounds__(CTA_THREADS, 3)
void cbert_short_kernel(const float* __restrict__ reps,
                        const float* __restrict__ weight,
                        const float* __restrict__ bias,
                        const int* __restrict__ sense_ids,
                        const int* __restrict__ target_ids,
                        float* __restrict__ out, int out_size) {
    __shared__ __align__(16) float s_reps[D_SZ];   // 3 KB

    const int lane = threadIdx.x & 31;
    const int warp = threadIdx.x >> 5;
    const int b  = blockIdx.x;                     // sample (same for whole CTA)
    const int k0 = warp * ITEMS_PER_WARP;          // this warp's candidates

    // Stage reps[b] into smem: 192 float4, 256 threads -> <=1 LDG each.
    {
        const float4* src = reinterpret_cast<const float4*>(reps + (size_t)b * D_SZ);
        float4* dst = reinterpret_cast<float4*>(s_reps);
        if (threadIdx.x < D_SZ / 4) dst[threadIdx.x] = src[threadIdx.x];
    }

    // Warp-uniform candidate ids (one 16B load).
    const int4 idv = __ldg(reinterpret_cast<const int4*>(&sense_ids[b * K_SZ + k0]));
    const int ids[ITEMS_PER_WARP] = {idv.x, idv.y, idv.z, idv.w};

    __syncthreads();   // s_reps ready
    const float4* r4 = reinterpret_cast<const float4*>(s_reps);

    // Two pair-bursts: 12 front-batched LDG.128 (6 KB in flight) per burst.
    #pragma unroll
    for (int t = 0; t < ITEMS_PER_WARP / 2; ++t) {
        const int idA = ids[t * 2], idB = ids[t * 2 + 1];
        const bool vA = (idA >= 0 && idA < N_SENSES);
        const bool vB = (idB >= 0 && idB < N_SENSES);

        const float4* wA = reinterpret_cast<const float4*>(weight + (size_t)(vA ? idA : 0) * D_SZ);
        const float4* wB = reinterpret_cast<const float4*>(weight + (size_t)(vB ? idB : 0) * D_SZ);

        float4 bufA[6], bufB[6];
        #pragma unroll
        for (int j = 0; j < 6; ++j) {         // independent, front-batched
            if (vA) bufA[j] = wA[lane + 32 * j];
            if (vB) bufB[j] = wB[lane + 32 * j];
        }
        float biasA = vA ? __ldg(&bias[idA]) : 0.f;
        float biasB = vB ? __ldg(&bias[idB]) : 0.f;

        float accA = 0.f, accB = 0.f;
        #pragma unroll
        for (int j = 0; j < 6; ++j) {
            const float4 r = r4[lane + 32 * j];   // one LDS.128, reused twice
            if (vA) {
                accA = fmaf(bufA[j].x, r.x, accA);
                accA = fmaf(bufA[j].y, r.y, accA);
                accA = fmaf(bufA[j].z, r.z, accA);
                accA = fmaf(bufA[j].w, r.w, accA);
            }
            if (vB) {
                accB = fmaf(bufB[j].x, r.x, accB);
                accB = fmaf(bufB[j].y, r.y, accB);
                accB = fmaf(bufB[j].z, r.z, accB);
                accB = fmaf(bufB[j].w, r.w, accB);
            }
        }
        #pragma unroll
        for (int off = 16; off > 0; off >>= 1) {
            accA += __shfl_down_sync(0xFFFFFFFFu, accA, off);
            accB += __shfl_down_sync(0xFFFFFFFFu, accB, off);
        }
        if (lane == 0) {
            float2 lg;
            lg.x = vA ? accA + biasA : NEG_INF;
            lg.y = vB ? accB + biasB : NEG_INF;
            __stcg(reinterpret_cast<float2*>(&g_logits[b * K_SZ + k0 + t * 2]), lg);
        }
    }

    // ---- Count warp arrivals for sample b ----
    unsigned old = 0;
    if (lane == 0) {
        __threadfence();
        old = atomicInc(&g_cnt[b], WARPS_PER_CTA - 1);   // wraps after 8
    }
    old = __shfl_sync(0xFFFFFFFFu, old, 0);
    if (old != WARPS_PER_CTA - 1) return;

    // ---- Phase 2: last warp of sample b -> 32-wide masked softmax ----
    __threadfence();
    float v = __ldcg(&g_logits[b * K_SZ + lane]);

    float mval = v; int midx = lane;
    #pragma unroll
    for (int off = 16; off > 0; off >>= 1) {
        float ov = __shfl_down_sync(0xFFFFFFFFu, mval, off);
        int   oi = __shfl_down_sync(0xFFFFFFFFu, midx, off);
        if (ov > mval || (ov == mval && oi < midx)) { mval = ov; midx = oi; }
    }
    mval = __shfl_sync(0xFFFFFFFFu, mval, 0);
    midx = __shfl_sync(0xFFFFFFFFu, midx, 0);

    float e = expf(v - mval);
    #pragma unroll
    for (int off = 16; off > 0; off >>= 1)
        e += __shfl_down_sync(0xFFFFFFFFu, e, off);
    float sumexp = __shfl_sync(0xFFFFFFFFu, e, 0);

    const int tgt = target_ids[b];
    float tlogit = __shfl_sync(0xFFFFFFFFu, v, tgt & 31);

    unsigned done2 = 0;
    if (lane == 0) {
        float nll = -(tlogit - mval - logf(sumexp));
        __stcg(&g_nll[b], nll);
        if (1 + b < out_size) out[1 + b] = (midx == tgt) ? 1.0f : 0.0f;
        __threadfence();
        done2 = atomicInc(&g_done, B_SZ - 1);            // wraps after 512
    }
    done2 = __shfl_sync(0xFFFFFFFFu, done2, 0);
    if (done2 != B_SZ - 1) return;

    // ---- Phase 3: deterministic fixed-order mean of 512 NLLs ----
    __threadfence();
    float acc = 0.f;
    #pragma unroll
    for (int i = 0; i < B_SZ / 32; ++i)
        acc += __ldcg(&g_nll[lane + 32 * i]);
    #pragma unroll
    for (int off = 16; off > 0; off >>= 1)
        acc += __shfl_down_sync(0xFFFFFFFFu, acc, off);
    if (lane == 0 && out_size > 0) out[0] = acc / (float)B_SZ;
}

extern "C" void kernel_launch(void* const* d_in, const int* in_sizes, int n_in,
                              void* d_out, int out_size) {
    const float* reps = (const float*)d_in[0];
    const float* weight = (const float*)d_in[1];
    const float* bias = (const float*)d_in[2];
    const int* sense_ids = (const int*)d_in[3];
    const int* target_ids = (const int*)d_in[4];
    float* out = (float*)d_out;

    cbert_short_kernel<<<GRID_CTAS, CTA_THREADS>>>(reps, weight, bias,
                                                   sense_ids, target_ids,
                                                   out, out_size);
}

// round 16
// speedup vs baseline: 1.0022x; 1.0022x over previous
#include <cuda_runtime.h>
#include <cuda_bf16.h>
#include <math.h>
#include <cstdint>

#define B_SZ 512
#define K_SZ 32
#define D_SZ 768
#define N_SENSES 200000
#define NEG_INF -1e30f

#define WARPS_PER_CTA 8
#define CTA_THREADS (WARPS_PER_CTA * 32)       // 256
#define ITEMS_PER_WARP (K_SZ / WARPS_PER_CTA)  // 4 candidates per warp
#define GRID_CTAS B_SZ                         // 1 sample per CTA -> 512 CTAs

// Global scratch. Counters use atomicInc wrap -> self-reset each full launch,
// deterministic under graph replay.
__device__ float    g_logits[B_SZ * K_SZ];
__device__ float    g_nll[B_SZ];
__device__ unsigned g_cnt[B_SZ];     // wraps at WARPS_PER_CTA-1 (8 warp arrivals)
__device__ unsigned g_done = 0;      // wraps at B_SZ-1

__global__ __launch_bounds__(CTA_THREADS, 2)
void cbert_i4_kernel(const float* __restrict__ reps,
                     const float* __restrict__ weight,
                     const float* __restrict__ bias,
                     const int* __restrict__ sense_ids,
                     const int* __restrict__ target_ids,
                     float* __restrict__ out, int out_size) {
    const int lane = threadIdx.x & 31;
    const int warp = threadIdx.x >> 5;
    const int b  = blockIdx.x;                 // sample (same for whole CTA)
    const int k0 = warp * ITEMS_PER_WARP;      // this warp's 4 candidates

    // Warp-uniform candidate ids (one 16B load).
    const int4 idv = __ldg(reinterpret_cast<const int4*>(&sense_ids[b * K_SZ + k0]));
    const int ids[ITEMS_PER_WARP] = {idv.x, idv.y, idv.z, idv.w};

    // reps[b] in registers — 6 independent LDG.128 (L2-hot after first warp).
    // No barrier: ptxas can merge these with the first weight burst below.
    const float4* rp = reinterpret_cast<const float4*>(reps + (size_t)b * D_SZ);
    float4 r[6];
    #pragma unroll
    for (int j = 0; j < 6; ++j) r[j] = __ldg(&rp[lane + 32 * j]);

    // Two pair-epochs: 12 front-batched LDG.128 (6 KB in flight) per epoch.
    #pragma unroll
    for (int t = 0; t < ITEMS_PER_WARP / 2; ++t) {
        const int idA = ids[t * 2], idB = ids[t * 2 + 1];
        const bool vA = (idA >= 0 && idA < N_SENSES);
        const bool vB = (idB >= 0 && idB < N_SENSES);

        const float4* wA = reinterpret_cast<const float4*>(weight + (size_t)(vA ? idA : 0) * D_SZ);
        const float4* wB = reinterpret_cast<const float4*>(weight + (size_t)(vB ? idB : 0) * D_SZ);

        float4 bufA[6], bufB[6];
        #pragma unroll
        for (int j = 0; j < 6; ++j) {          // independent, front-batched
            if (vA) bufA[j] = __ldcs(&wA[lane + 32 * j]);   // read-once stream
            if (vB) bufB[j] = __ldcs(&wB[lane + 32 * j]);
        }
        float biasA = vA ? __ldg(&bias[idA]) : 0.f;
        float biasB = vB ? __ldg(&bias[idB]) : 0.f;

        float accA = 0.f, accB = 0.f;
        #pragma unroll
        for (int j = 0; j < 6; ++j) {
            if (vA) {
                accA = fmaf(bufA[j].x, r[j].x, accA);
                accA = fmaf(bufA[j].y, r[j].y, accA);
                accA = fmaf(bufA[j].z, r[j].z, accA);
                accA = fmaf(bufA[j].w, r[j].w, accA);
            }
            if (vB) {
                accB = fmaf(bufB[j].x, r[j].x, accB);
                accB = fmaf(bufB[j].y, r[j].y, accB);
                accB = fmaf(bufB[j].z, r[j].z, accB);
                accB = fmaf(bufB[j].w, r[j].w, accB);
            }
        }
        #pragma unroll
        for (int off = 16; off > 0; off >>= 1) {
            accA += __shfl_down_sync(0xFFFFFFFFu, accA, off);
            accB += __shfl_down_sync(0xFFFFFFFFu, accB, off);
        }
        if (lane == 0) {
            float2 lg;
            lg.x = vA ? accA + biasA : NEG_INF;
            lg.y = vB ? accB + biasB : NEG_INF;
            __stcg(reinterpret_cast<float2*>(&g_logits[b * K_SZ + k0 + t * 2]), lg);
        }
    }

    // ---- Count warp arrivals for sample b ----
    unsigned old = 0;
    if (lane == 0) {
        __threadfence();
        old = atomicInc(&g_cnt[b], WARPS_PER_CTA - 1);   // wraps after 8
    }
    old = __shfl_sync(0xFFFFFFFFu, old, 0);
    if (old != WARPS_PER_CTA - 1) return;

    // ---- Phase 2: last warp of sample b -> 32-wide masked softmax ----
    __threadfence();
    float v = __ldcg(&g_logits[b * K_SZ + lane]);

    float mval = v; int midx = lane;
    #pragma unroll
    for (int off = 16; off > 0; off >>= 1) {
        float ov = __shfl_down_sync(0xFFFFFFFFu, mval, off);
        int   oi = __shfl_down_sync(0xFFFFFFFFu, midx, off);
        if (ov > mval || (ov == mval && oi < midx)) { mval = ov; midx = oi; }
    }
    mval = __shfl_sync(0xFFFFFFFFu, mval, 0);
    midx = __shfl_sync(0xFFFFFFFFu, midx, 0);

    float e = expf(v - mval);
    #pragma unroll
    for (int off = 16; off > 0; off >>= 1)
        e += __shfl_down_sync(0xFFFFFFFFu, e, off);
    float sumexp = __shfl_sync(0xFFFFFFFFu, e, 0);

    const int tgt = target_ids[b];
    float tlogit = __shfl_sync(0xFFFFFFFFu, v, tgt & 31);

    unsigned done2 = 0;
    if (lane == 0) {
        float nll = -(tlogit - mval - logf(sumexp));
        __stcg(&g_nll[b], nll);
        if (1 + b < out_size) out[1 + b] = (midx == tgt) ? 1.0f : 0.0f;
        __threadfence();
        done2 = atomicInc(&g_done, B_SZ - 1);            // wraps after 512
    }
    done2 = __shfl_sync(0xFFFFFFFFu, done2, 0);
    if (done2 != B_SZ - 1) return;

    // ---- Phase 3: deterministic fixed-order mean of 512 NLLs ----
    __threadfence();
    float acc = 0.f;
    #pragma unroll
    for (int i = 0; i < B_SZ / 32; ++i)
        acc += __ldcg(&g_nll[lane + 32 * i]);
    #pragma unroll
    for (int off = 16; off > 0; off >>= 1)
        acc += __shfl_down_sync(0xFFFFFFFFu, acc, off);
    if (lane == 0 && out_size > 0) out[0] = acc / (float)B_SZ;
}

extern "C" void kernel_launch(void* const* d_in, const int* in_sizes, int n_in,
                              void* d_out, int out_size) {
    const float* reps = (const float*)d_in[0];
    const float* weight = (const float*)d_in[1];
    const float* bias = (const float*)d_in[2];
    const int* sense_ids = (const int*)d_in[3];
    const int* target_ids = (const int*)d_in[4];
    float* out = (float*)d_out;

    cbert_i4_kernel<<<GRID_CTAS, CTA_THREADS>>>(reps, weight, bias,
                                                sense_ids, target_ids,
                                                out, out_size);
}

// round 17
// speedup vs baseline: 1.3851x; 1.3821x over previous
#include <cuda_runtime.h>
#include <cuda_bf16.h>
#include <math.h>
#include <cstdint>

#define B_SZ 512
#define K_SZ 32
#define D_SZ 768
#define N_SENSES 200000
#define NEG_INF -1e30f

#define WARPS_PER_SAMPLE 4
#define ITEMS_PER_WARP (K_SZ / WARPS_PER_SAMPLE)   // 8
#define WARPS_PER_CTA 8
#define CTA_THREADS (WARPS_PER_CTA * 32)
#define SAMPLES_PER_CTA (WARPS_PER_CTA / WARPS_PER_SAMPLE)  // 2
#define GRID_CTAS (B_SZ / SAMPLES_PER_CTA)         // 256

// Global scratch. Counters use atomicInc wrap -> self-reset each full launch,
// deterministic under graph replay.
__device__ float    g_logits[B_SZ * K_SZ];
__device__ float    g_nll[B_SZ];
__device__ unsigned g_cnt[B_SZ];     // wraps at WARPS_PER_SAMPLE-1
__device__ unsigned g_done = 0;      // wraps at B_SZ-1

__global__ __launch_bounds__(CTA_THREADS, 2)
void cbert_interleave_kernel(const float* __restrict__ reps,
                             const float* __restrict__ weight,
                             const float* __restrict__ bias,
                             const int* __restrict__ sense_ids,
                             const int* __restrict__ target_ids,
                             float* __restrict__ out, int out_size) {
    const int lane = threadIdx.x & 31;
    const int warp = threadIdx.x >> 5;
    const int b    = blockIdx.x * SAMPLES_PER_CTA + (warp >> 2);  // sample
    const int widx = warp & 3;   // warp index within sample (0..3)

    // reps[b] in registers, reused for all 8 candidates (L2-hot after 1st warp).
    const float4* rp = reinterpret_cast<const float4*>(reps + (size_t)b * D_SZ);
    float4 r[6];
    #pragma unroll
    for (int j = 0; j < 6; ++j) r[j] = __ldg(&rp[lane + 32 * j]);

    // STRIDED candidate assignment: k = widx + 4*i. Padding lives at high k,
    // so every warp gets ~length/4 valid rows -> balanced warp workloads.
    int ids[ITEMS_PER_WARP];
    #pragma unroll
    for (int i = 0; i < ITEMS_PER_WARP; ++i)
        ids[i] = __ldg(&sense_ids[b * K_SZ + widx + 4 * i]);

    // Process candidates in pairs: 12 LDG.128 in flight per iteration.
    #pragma unroll
    for (int i = 0; i < ITEMS_PER_WARP; i += 2) {
        const int idA = ids[i], idB = ids[i + 1];
        const bool vA = (idA >= 0 && idA < N_SENSES);
        const bool vB = (idB >= 0 && idB < N_SENSES);

        const float4* wA = reinterpret_cast<const float4*>(weight + (size_t)(vA ? idA : 0) * D_SZ);
        const float4* wB = reinterpret_cast<const float4*>(weight + (size_t)(vB ? idB : 0) * D_SZ);

        float4 bufA[6], bufB[6];
        #pragma unroll
        for (int j = 0; j < 6; ++j) {         // front-batched, independent
            if (vA) bufA[j] = wA[lane + 32 * j];
            if (vB) bufB[j] = wB[lane + 32 * j];
        }
        float biasA = vA ? __ldg(&bias[idA]) : 0.f;
        float biasB = vB ? __ldg(&bias[idB]) : 0.f;

        float accA = 0.f, accB = 0.f;
        #pragma unroll
        for (int j = 0; j < 6; ++j) {
            if (vA) {
                accA = fmaf(bufA[j].x, r[j].x, accA);
                accA = fmaf(bufA[j].y, r[j].y, accA);
                accA = fmaf(bufA[j].z, r[j].z, accA);
                accA = fmaf(bufA[j].w, r[j].w, accA);
            }
            if (vB) {
                accB = fmaf(bufB[j].x, r[j].x, accB);
                accB = fmaf(bufB[j].y, r[j].y, accB);
                accB = fmaf(bufB[j].z, r[j].z, accB);
                accB = fmaf(bufB[j].w, r[j].w, accB);
            }
        }
        #pragma unroll
        for (int off = 16; off > 0; off >>= 1) {
            accA += __shfl_down_sync(0xFFFFFFFFu, accA, off);
            accB += __shfl_down_sync(0xFFFFFFFFu, accB, off);
        }
        if (lane == 0) {
            __stcg(&g_logits[b * K_SZ + widx + 4 * i],       vA ? accA + biasA : NEG_INF);
            __stcg(&g_logits[b * K_SZ + widx + 4 * (i + 1)], vB ? accB + biasB : NEG_INF);
        }
    }

    // ---- Count warp arrivals for sample b ----
    unsigned old = 0;
    if (lane == 0) {
        __threadfence();
        old = atomicInc(&g_cnt[b], WARPS_PER_SAMPLE - 1);   // wraps after 4
    }
    old = __shfl_sync(0xFFFFFFFFu, old, 0);
    if (old != WARPS_PER_SAMPLE - 1) return;

    // ---- Phase 2: last warp of sample b -> 32-wide masked softmax ----
    __threadfence();
    float v = __ldcg(&g_logits[b * K_SZ + lane]);

    float mval = v; int midx = lane;
    #pragma unroll
    for (int off = 16; off > 0; off >>= 1) {
        float ov = __shfl_down_sync(0xFFFFFFFFu, mval, off);
        int   oi = __shfl_down_sync(0xFFFFFFFFu, midx, off);
        if (ov > mval || (ov == mval && oi < midx)) { mval = ov; midx = oi; }
    }
    mval = __shfl_sync(0xFFFFFFFFu, mval, 0);
    midx = __shfl_sync(0xFFFFFFFFu, midx, 0);

    float e = expf(v - mval);
    #pragma unroll
    for (int off = 16; off > 0; off >>= 1)
        e += __shfl_down_sync(0xFFFFFFFFu, e, off);
    float sumexp = __shfl_sync(0xFFFFFFFFu, e, 0);

    const int tgt = target_ids[b];
    float tlogit = __shfl_sync(0xFFFFFFFFu, v, tgt & 31);

    unsigned done2 = 0;
    if (lane == 0) {
        float nll = -(tlogit - mval - logf(sumexp));
        __stcg(&g_nll[b], nll);
        if (1 + b < out_size) out[1 + b] = (midx == tgt) ? 1.0f : 0.0f;
        __threadfence();
        done2 = atomicInc(&g_done, B_SZ - 1);               // wraps after 512
    }
    done2 = __shfl_sync(0xFFFFFFFFu, done2, 0);
    if (done2 != B_SZ - 1) return;

    // ---- Phase 3: deterministic fixed-order mean of 512 NLLs ----
    __threadfence();
    float acc = 0.f;
    #pragma unroll
    for (int i = 0; i < B_SZ / 32; ++i)
        acc += __ldcg(&g_nll[lane + 32 * i]);
    #pragma unroll
    for (int off = 16; off > 0; off >>= 1)
        acc += __shfl_down_sync(0xFFFFFFFFu, acc, off);
    if (lane == 0 && out_size > 0) out[0] = acc / (float)B_SZ;
}

extern "C" void kernel_launch(void* const* d_in, const int* in_sizes, int n_in,
                              void* d_out, int out_size) {
    const float* reps = (const float*)d_in[0];
    const float* weight = (const float*)d_in[1];
    const float* bias = (const float*)d_in[2];
    const int* sense_ids = (const int*)d_in[3];
    const int* target_ids = (const int*)d_in[4];
    float* out = (float*)d_out;

    cbert_interleave_kernel<<<GRID_CTAS, CTA_THREADS>>>(reps, weight, bias,
                                                        sense_ids, target_ids,
                                                        out, out_size);
}